// round 2
// baseline (speedup 1.0000x reference)
#include <cuda_runtime.h>

#define N_NODES 50000
#define N_EDGES 800000
#define FDIM 128
#define TS 132   // activation smem row stride (floats)
#define GS 36    // gather tile smem row stride (floats)

// Scratch (no allocs allowed): segment accumulators
__device__ float g_agg[(size_t)N_NODES * FDIM];   // sum of m per node
__device__ float g_trans[N_NODES * 3];            // sum of trans per node
__device__ float g_cnt[N_NODES];                  // edge count per node

__device__ __forceinline__ float silu_f(float x) {
    return x / (1.f + __expf(-x));
}

// SMEM layout (words):
//   act1: 128*TS, act2: 128*TS, As: 128*GS, Ws: 32*TS,
//   s_rad:128, s_phi:128, s_diff:128*4, s_inv:128, s_row:128(int), s_col:128(int)
#define SMEM_WORDS (2*128*TS + 128*GS + 32*TS + 128 + 128 + 128*4 + 128 + 256)
#define SMEM_BYTES (SMEM_WORDS * 4)

// Generic K=128 layer: actOut = act(actIn @ W + bias), all in SMEM except W/bias.
// 256 threads, 16x16 grid, 8x8 microtile per thread.
__device__ __noinline__ void layer128(
    const float* actIn, const float* __restrict__ W,
    const float* __restrict__ bias, float* actOut, float* Ws,
    int er, int jc, int tid, bool do_silu)
{
    float acc[8][8];
#pragma unroll
    for (int j = 0; j < 8; j++) {
        float b = bias[jc + j];
#pragma unroll
        for (int i = 0; i < 8; i++) acc[i][j] = b;
    }
    for (int kt = 0; kt < 4; kt++) {
        __syncthreads();
#pragma unroll
        for (int q = 0; q < 4; q++) {
            int t = tid + q * 256;
            int k = t >> 5, jf = t & 31;
            ((float4*)(Ws + k * TS))[jf] =
                ((const float4*)(W + (kt * 32 + k) * FDIM))[jf];
        }
        __syncthreads();
#pragma unroll 2
        for (int k4 = 0; k4 < 8; k4++) {
            float4 av[8];
#pragma unroll
            for (int i = 0; i < 8; i++)
                av[i] = *(const float4*)(actIn + (er + i) * TS + kt * 32 + k4 * 4);
#pragma unroll
            for (int kk = 0; kk < 4; kk++) {
                const float* wr = Ws + (k4 * 4 + kk) * TS + jc;
                float4 b0 = *(const float4*)wr;
                float4 b1 = *(const float4*)(wr + 4);
                float bb[8] = {b0.x, b0.y, b0.z, b0.w, b1.x, b1.y, b1.z, b1.w};
#pragma unroll
                for (int i = 0; i < 8; i++) {
                    float a = kk == 0 ? av[i].x : kk == 1 ? av[i].y
                              : kk == 2 ? av[i].z : av[i].w;
#pragma unroll
                    for (int j = 0; j < 8; j++)
                        acc[i][j] = fmaf(a, bb[j], acc[i][j]);
                }
            }
        }
    }
    __syncthreads();
#pragma unroll
    for (int i = 0; i < 8; i++) {
#pragma unroll
        for (int j = 0; j < 8; j++) {
            float v = acc[i][j];
            if (do_silu) v = silu_f(v);
            actOut[(er + i) * TS + jc + j] = v;
        }
    }
    __syncthreads();
}

__global__ void zero_kernel() {
    int i = blockIdx.x * 256 + threadIdx.x;
    if (i < N_NODES * FDIM) g_agg[i] = 0.f;
    int j = i - N_NODES * FDIM;
    if (j >= 0 && j < N_NODES * 3) g_trans[j] = 0.f;
    int k = j - N_NODES * 3;
    if (k >= 0 && k < N_NODES) g_cnt[k] = 0.f;
}

__global__ __launch_bounds__(256, 1) void edge_kernel(
    const float* __restrict__ h, const float* __restrict__ coord,
    const float* __restrict__ mw0, const float* __restrict__ mb0,
    const float* __restrict__ mw1, const float* __restrict__ mb1,
    const float* __restrict__ cw0, const float* __restrict__ cb0,
    const float* __restrict__ cw1, const float* __restrict__ cb1,
    const float* __restrict__ cw2,
    const int* __restrict__ edge_index)   // int32! (JAX x64 disabled)
{
    extern __shared__ float sm[];
    float* act1 = sm;
    float* act2 = act1 + 128 * TS;
    float* As   = act2 + 128 * TS;
    float* Ws   = As + 128 * GS;
    float* s_rad = Ws + 32 * TS;
    float* s_phi = s_rad + 128;
    float* s_diff = s_phi + 128;          // [128][4]
    float* s_inv  = s_diff + 128 * 4;     // unused here
    int* s_row = (int*)(s_inv + 128);
    int* s_col = s_row + 128;

    int tid = threadIdx.x;
    int ebase = blockIdx.x * 128;

    if (tid < 128) {
        int e = ebase + tid;
        int r = edge_index[2 * e];
        int c = edge_index[2 * e + 1];
        s_row[tid] = r;
        s_col[tid] = c;
        float dx = coord[r * 3 + 0] - coord[c * 3 + 0];
        float dy = coord[r * 3 + 1] - coord[c * 3 + 1];
        float dz = coord[r * 3 + 2] - coord[c * 3 + 2];
        s_diff[tid * 4 + 0] = dx;
        s_diff[tid * 4 + 1] = dy;
        s_diff[tid * 4 + 2] = dz;
        s_rad[tid] = dx * dx + dy * dy + dz * dz;
    }
    __syncthreads();

    int ty = tid >> 4, tx = tid & 15;
    int er = ty * 8, jc = tx * 8;

    // ---- Layer 1: edge_in(257) @ mw0 + mb0, silu -> act1 ----
    {
        float acc[8][8];
        float wl[8];
#pragma unroll
        for (int j = 0; j < 8; j++) wl[j] = mw0[256 * FDIM + jc + j];
#pragma unroll
        for (int i = 0; i < 8; i++) {
            float rad = s_rad[er + i];
#pragma unroll
            for (int j = 0; j < 8; j++)
                acc[i][j] = mb0[jc + j] + rad * wl[j];   // radial row folded in
        }
        int ge = tid >> 1, half = tid & 1;
        for (int kt = 0; kt < 8; kt++) {
            __syncthreads();
            {   // gather A tile: k<128 -> h[row], else h[col]
                int idx = (kt < 4) ? s_row[ge] : s_col[ge];
                const float4* src = (const float4*)(h + (long long)idx * FDIM
                                                    + (kt & 3) * 32 + half * 16);
                float4* dst = (float4*)(As + ge * GS + half * 16);
#pragma unroll
                for (int q = 0; q < 4; q++) dst[q] = src[q];
            }
#pragma unroll
            for (int q = 0; q < 4; q++) {
                int t = tid + q * 256;
                int k = t >> 5, jf = t & 31;
                ((float4*)(Ws + k * TS))[jf] =
                    ((const float4*)(mw0 + (kt * 32 + k) * FDIM))[jf];
            }
            __syncthreads();
#pragma unroll 2
            for (int k4 = 0; k4 < 8; k4++) {
                float4 av[8];
#pragma unroll
                for (int i = 0; i < 8; i++)
                    av[i] = *(const float4*)(As + (er + i) * GS + k4 * 4);
#pragma unroll
                for (int kk = 0; kk < 4; kk++) {
                    const float* wr = Ws + (k4 * 4 + kk) * TS + jc;
                    float4 b0 = *(const float4*)wr;
                    float4 b1 = *(const float4*)(wr + 4);
                    float bb[8] = {b0.x, b0.y, b0.z, b0.w,
                                   b1.x, b1.y, b1.z, b1.w};
#pragma unroll
                    for (int i = 0; i < 8; i++) {
                        float a = kk == 0 ? av[i].x : kk == 1 ? av[i].y
                                  : kk == 2 ? av[i].z : av[i].w;
#pragma unroll
                        for (int j = 0; j < 8; j++)
                            acc[i][j] = fmaf(a, bb[j], acc[i][j]);
                    }
                }
            }
        }
        __syncthreads();
#pragma unroll
        for (int i = 0; i < 8; i++)
#pragma unroll
            for (int j = 0; j < 8; j++)
                act1[(er + i) * TS + jc + j] = silu_f(acc[i][j]);
        __syncthreads();
    }

    // ---- Layer 2: m = silu(act1 @ mw1 + mb1) -> act2 ----
    layer128(act1, mw1, mb1, act2, Ws, er, jc, tid, true);

    // scatter m into g_agg (segment sum)
    {
        int e = tid >> 1;
        int node = s_row[e];
        int jb = (tid & 1) * 64;
        const float* mrow = act2 + e * TS + jb;
        float* dst = g_agg + node * FDIM + jb;
#pragma unroll 8
        for (int j = 0; j < 64; j++) atomicAdd(dst + j, mrow[j]);
    }

    // ---- coord MLP: phi1 = silu(m@cw0+cb0) -> act1; phi2 = silu(@cw1+cb1) -> act2
    layer128(act2, cw0, cb0, act1, Ws, er, jc, tid, true);
    layer128(act1, cw1, cb1, act2, Ws, er, jc, tid, true);

    // phi_x = phi2 @ cw2 (scalar), trans = coord_diff*phi_x, scatter + count
    if (tid < 128) {
        float s = 0.f;
#pragma unroll 8
        for (int j = 0; j < 128; j += 4) {
            float4 p = *(const float4*)(act2 + tid * TS + j);
            s += p.x * cw2[j] + p.y * cw2[j + 1] + p.z * cw2[j + 2] + p.w * cw2[j + 3];
        }
        int node = s_row[tid];
        atomicAdd(&g_trans[node * 3 + 0], s_diff[tid * 4 + 0] * s);
        atomicAdd(&g_trans[node * 3 + 1], s_diff[tid * 4 + 1] * s);
        atomicAdd(&g_trans[node * 3 + 2], s_diff[tid * 4 + 2] * s);
        atomicAdd(&g_cnt[node], 1.f);
    }
}

__global__ __launch_bounds__(256, 1) void node_kernel(
    const float* __restrict__ h, const float* __restrict__ coord,
    const float* __restrict__ nw0, const float* __restrict__ nb0,
    const float* __restrict__ nw1, const float* __restrict__ nb1,
    const float* __restrict__ nw2, const float* __restrict__ nb2,
    float* __restrict__ out)
{
    extern __shared__ float sm[];
    float* act1 = sm;
    float* act2 = act1 + 128 * TS;
    float* As   = act2 + 128 * TS;
    float* Ws   = As + 128 * GS;
    float* s_rad = Ws + 32 * TS;
    float* s_phi = s_rad + 128;
    float* s_diff = s_phi + 128;
    float* s_inv  = s_diff + 128 * 4;
    int* s_row = (int*)(s_inv + 128);

    int tid = threadIdx.x;
    int n0 = blockIdx.x * 128;

    if (tid < 128) {
        int n = n0 + tid;
        int nc = (n < N_NODES) ? n : (N_NODES - 1);
        s_row[tid] = nc;
        float c = (n < N_NODES) ? g_cnt[n] : 1.f;
        s_inv[tid] = 1.f / fmaxf(c, 1.f);
    }
    __syncthreads();

    int ty = tid >> 4, tx = tid & 15;
    int er = ty * 8, jc = tx * 8;

    // ---- Layer 1: [h | agg_mean](256) @ nw0 + nb0, silu -> act1 ----
    {
        float acc[8][8];
#pragma unroll
        for (int j = 0; j < 8; j++) {
            float b = nb0[jc + j];
#pragma unroll
            for (int i = 0; i < 8; i++) acc[i][j] = b;
        }
        int ge = tid >> 1, half = tid & 1;
        for (int kt = 0; kt < 8; kt++) {
            __syncthreads();
            {
                int nc = s_row[ge];
                const float* base = (kt < 4) ? (h + (long long)nc * FDIM)
                                             : (g_agg + (long long)nc * FDIM);
                const float4* src = (const float4*)(base + (kt & 3) * 32 + half * 16);
                float scv = (kt < 4) ? 1.f : s_inv[ge];
                float4* dst = (float4*)(As + ge * GS + half * 16);
#pragma unroll
                for (int q = 0; q < 4; q++) {
                    float4 v = src[q];
                    v.x *= scv; v.y *= scv; v.z *= scv; v.w *= scv;
                    dst[q] = v;
                }
            }
#pragma unroll
            for (int q = 0; q < 4; q++) {
                int t = tid + q * 256;
                int k = t >> 5, jf = t & 31;
                ((float4*)(Ws + k * TS))[jf] =
                    ((const float4*)(nw0 + (kt * 32 + k) * FDIM))[jf];
            }
            __syncthreads();
#pragma unroll 2
            for (int k4 = 0; k4 < 8; k4++) {
                float4 av[8];
#pragma unroll
                for (int i = 0; i < 8; i++)
                    av[i] = *(const float4*)(As + (er + i) * GS + k4 * 4);
#pragma unroll
                for (int kk = 0; kk < 4; kk++) {
                    const float* wr = Ws + (k4 * 4 + kk) * TS + jc;
                    float4 b0 = *(const float4*)wr;
                    float4 b1 = *(const float4*)(wr + 4);
                    float bb[8] = {b0.x, b0.y, b0.z, b0.w,
                                   b1.x, b1.y, b1.z, b1.w};
#pragma unroll
                    for (int i = 0; i < 8; i++) {
                        float a = kk == 0 ? av[i].x : kk == 1 ? av[i].y
                                  : kk == 2 ? av[i].z : av[i].w;
#pragma unroll
                        for (int j = 0; j < 8; j++)
                            acc[i][j] = fmaf(a, bb[j], acc[i][j]);
                    }
                }
            }
        }
        __syncthreads();
#pragma unroll
        for (int i = 0; i < 8; i++)
#pragma unroll
            for (int j = 0; j < 8; j++)
                act1[(er + i) * TS + jc + j] = silu_f(acc[i][j]);
        __syncthreads();
    }

    layer128(act1, nw1, nb1, act2, Ws, er, jc, tid, true);
    layer128(act2, nw2, nb2, act1, Ws, er, jc, tid, false);

    // h_new = h + out
#pragma unroll
    for (int i = 0; i < 8; i++) {
        int n = n0 + er + i;
        if (n < N_NODES) {
#pragma unroll
            for (int j = 0; j < 8; j++)
                out[(long long)n * FDIM + jc + j] =
                    h[(long long)n * FDIM + jc + j] + act1[(er + i) * TS + jc + j];
        }
    }
    // coord_new = coord + trans_mean
    if (tid < 128) {
        int n = n0 + tid;
        if (n < N_NODES) {
            float inv = s_inv[tid];
            float* co = out + (long long)N_NODES * FDIM + n * 3;
            co[0] = coord[n * 3 + 0] + g_trans[n * 3 + 0] * inv;
            co[1] = coord[n * 3 + 1] + g_trans[n * 3 + 1] * inv;
            co[2] = coord[n * 3 + 2] + g_trans[n * 3 + 2] * inv;
        }
    }
}

extern "C" void kernel_launch(void* const* d_in, const int* in_sizes, int n_in,
                              void* d_out, int out_size)
{
    const float* h   = (const float*)d_in[0];
    const float* coord = (const float*)d_in[1];
    const float* mw0 = (const float*)d_in[2];
    const float* mb0 = (const float*)d_in[3];
    const float* mw1 = (const float*)d_in[4];
    const float* mb1 = (const float*)d_in[5];
    const float* nw0 = (const float*)d_in[6];
    const float* nb0 = (const float*)d_in[7];
    const float* nw1 = (const float*)d_in[8];
    const float* nb1 = (const float*)d_in[9];
    const float* nw2 = (const float*)d_in[10];
    const float* nb2 = (const float*)d_in[11];
    const float* cw0 = (const float*)d_in[12];
    const float* cb0 = (const float*)d_in[13];
    const float* cw1 = (const float*)d_in[14];
    const float* cb1 = (const float*)d_in[15];
    const float* cw2 = (const float*)d_in[16];
    const int* ei = (const int*)d_in[17];
    float* out = (float*)d_out;

    cudaFuncSetAttribute(edge_kernel,
                         cudaFuncAttributeMaxDynamicSharedMemorySize, SMEM_BYTES);
    cudaFuncSetAttribute(node_kernel,
                         cudaFuncAttributeMaxDynamicSharedMemorySize, SMEM_BYTES);

    int totalz = N_NODES * FDIM + N_NODES * 3 + N_NODES;
    zero_kernel<<<(totalz + 255) / 256, 256>>>();
    edge_kernel<<<N_EDGES / 128, 256, SMEM_BYTES>>>(
        h, coord, mw0, mb0, mw1, mb1, cw0, cb0, cw1, cb1, cw2, ei);
    node_kernel<<<(N_NODES + 127) / 128, 256, SMEM_BYTES>>>(
        h, coord, nw0, nb0, nw1, nb1, nw2, nb2, out);
}

// round 4
// speedup vs baseline: 1.8684x; 1.8684x over previous
#include <cuda_runtime.h>
#include <cstdint>

#define N_NODES 50000
#define N_EDGES 800000
#define SA 132   // activation smem row stride (floats)
#define SW 132   // weight smem row stride (floats)

// ---------------- device scratch (no allocs allowed) ----------------
__device__ __align__(16) float g_agg[(size_t)N_NODES * 128];
__device__ __align__(16) float g_trans[N_NODES * 3];
__device__ float g_cnt[N_NODES];
// 9 pre-transposed (n-major), k-permuted, tf32-rounded 128x128 tiles:
// slot: 0=mw0[0:128) 1=mw0[128:256) 2=mw1 3=cw0 4=cw1 5=nw0[0:128) 6=nw0[128:256) 7=nw1 8=nw2
__device__ __align__(16) float g_wprep[9 * 16384];

// ---------------- helpers ----------------
static __device__ __forceinline__ float totf32(float x) {
    uint32_t u; asm("cvt.rna.tf32.f32 %0, %1;" : "=r"(u) : "f"(x));
    return __uint_as_float(u);
}
static __device__ __forceinline__ uint32_t fu(float x) { return __float_as_uint(x); }
static __device__ __forceinline__ float silu_f(float x) {
    return __fdividef(x, 1.f + __expf(-x));
}

static __device__ __forceinline__ void mma8(float d[4],
    uint32_t a0, uint32_t a1, uint32_t a2, uint32_t a3, uint32_t b0, uint32_t b1)
{
    asm volatile("mma.sync.aligned.m16n8k8.row.col.f32.tf32.tf32.f32 "
        "{%0,%1,%2,%3}, {%4,%5,%6,%7}, {%8,%9}, {%0,%1,%2,%3};"
        : "+f"(d[0]), "+f"(d[1]), "+f"(d[2]), "+f"(d[3])
        : "r"(a0), "r"(a1), "r"(a2), "r"(a3), "r"(b0), "r"(b1));
}

// 128x128x128 GEMM tile: warp (mband, nhalf) computes rows [mband*32, +32) x cols [nhalf*64, +64).
// actX: [row][kperm] stride SA ; Wsm: [n][kperm] stride SW (both k-pair-interleaved).
static __device__ __forceinline__ void gemm_tile(
    const float* actX, const float* Wsm, float acc[2][8][4],
    int mband, int nhalf, int lid)
{
    int gr = lid >> 2, j = lid & 3;
    const float* a0p = actX + (mband * 32 + gr) * SA + 2 * j;
    const float* b0p = Wsm + (nhalf * 64 + gr) * SW + 2 * j;
#pragma unroll 4
    for (int ks = 0; ks < 16; ks++) {
        int ko = ks * 8;
        float2 x0 = *(const float2*)(a0p + ko);            // rows mband*32+gr     : (a0,a2)
        float2 x8 = *(const float2*)(a0p + 8 * SA + ko);   // +8                   : (a1,a3)
        float2 y0 = *(const float2*)(a0p + 16 * SA + ko);  // mf=1
        float2 y8 = *(const float2*)(a0p + 24 * SA + ko);
#pragma unroll
        for (int nf = 0; nf < 8; nf++) {
            float2 b = *(const float2*)(b0p + nf * 8 * SW + ko);  // (b0,b1)
            mma8(acc[0][nf], fu(x0.x), fu(x8.x), fu(x0.y), fu(x8.y), fu(b.x), fu(b.y));
            mma8(acc[1][nf], fu(y0.x), fu(y8.x), fu(y0.y), fu(y8.y), fu(b.x), fu(b.y));
        }
    }
}

#define ZERO_ACC(acc) do { \
    _Pragma("unroll") for (int _a = 0; _a < 2; _a++) \
    _Pragma("unroll") for (int _b = 0; _b < 8; _b++) \
    _Pragma("unroll") for (int _c = 0; _c < 4; _c++) acc[_a][_b][_c] = 0.f; } while (0)

// gather 128 rows (idx[row]) of 128 floats, tf32-round (+optional scale),
// store k-pair-interleaved: within each 8-block, src cols [0..7] -> [0,2,4,6,1,3,5,7] positions
static __device__ __forceinline__ void gatherA(
    float* dst, const float* __restrict__ base, const int* idx, int tid,
    const float* s_scale)
{
    int row = tid >> 1, half = tid & 1;
    const float4* src = (const float4*)(base + (size_t)idx[row] * 128 + half * 64);
    float* d = dst + row * SA + half * 64;
    float s = s_scale ? s_scale[row] : 1.f;
#pragma unroll
    for (int blk = 0; blk < 8; blk++) {
        float4 lo = src[blk * 2];
        float4 hi = src[blk * 2 + 1];
        lo.x = totf32(lo.x * s); lo.y = totf32(lo.y * s);
        lo.z = totf32(lo.z * s); lo.w = totf32(lo.w * s);
        hi.x = totf32(hi.x * s); hi.y = totf32(hi.y * s);
        hi.z = totf32(hi.z * s); hi.w = totf32(hi.w * s);
        *(float4*)(d + blk * 8)     = make_float4(lo.x, hi.x, lo.y, hi.y);
        *(float4*)(d + blk * 8 + 4) = make_float4(lo.z, hi.z, lo.w, hi.w);
    }
}

// copy one prepared 128x128 weight tile (dense) into smem (stride SW)
static __device__ __forceinline__ void fillW(
    float* Wsm, const float* __restrict__ gp, int tid)
{
    int n = tid >> 1, half = tid & 1;
    const float4* s = (const float4*)(gp + n * 128 + half * 64);
    float4* d = (float4*)(Wsm + n * SW + half * 64);
#pragma unroll
    for (int q = 0; q < 16; q++) d[q] = s[q];
}

// epilogue -> permuted store for next GEMM. RAD adds rad*wrad; SCAT scatters to g_agg.
template<bool RAD, bool SCAT>
static __device__ __forceinline__ void epi_perm(
    float acc[2][8][4], float* actOut, const float* __restrict__ bias,
    const float* __restrict__ wrad, const float* s_rad, const int* s_node,
    int mband, int nhalf, int lid)
{
    int gr = lid >> 2, j = lid & 3;
    int p0 = (j < 2) ? 4 * j : 4 * j - 7;  // perm(2j); perm(2j+1) = p0+2
#pragma unroll
    for (int mf = 0; mf < 2; mf++) {
        int r0 = mband * 32 + mf * 16 + gr;
        int r1 = r0 + 8;
        float rad0 = RAD ? s_rad[r0] : 0.f;
        float rad1 = RAD ? s_rad[r1] : 0.f;
        int n0 = SCAT ? s_node[r0] : 0;
        int n1 = SCAT ? s_node[r1] : 0;
#pragma unroll
        for (int nf = 0; nf < 8; nf++) {
            int col = nhalf * 64 + nf * 8 + 2 * j;
            float b0 = __ldg(bias + col), b1 = __ldg(bias + col + 1);
            float v00 = acc[mf][nf][0] + b0;
            float v01 = acc[mf][nf][1] + b1;
            float v10 = acc[mf][nf][2] + b0;
            float v11 = acc[mf][nf][3] + b1;
            if (RAD) {
                float w0 = __ldg(wrad + col), w1 = __ldg(wrad + col + 1);
                v00 += rad0 * w0; v01 += rad0 * w1;
                v10 += rad1 * w0; v11 += rad1 * w1;
            }
            v00 = silu_f(v00); v01 = silu_f(v01);
            v10 = silu_f(v10); v11 = silu_f(v11);
            if (SCAT) {
                asm volatile("red.global.add.v2.f32 [%0], {%1, %2};" ::
                    "l"(g_agg + (size_t)n0 * 128 + col), "f"(v00), "f"(v01) : "memory");
                asm volatile("red.global.add.v2.f32 [%0], {%1, %2};" ::
                    "l"(g_agg + (size_t)n1 * 128 + col), "f"(v10), "f"(v11) : "memory");
            }
            int pp = nhalf * 64 + nf * 8 + p0;
            actOut[r0 * SA + pp]     = totf32(v00);
            actOut[r0 * SA + pp + 2] = totf32(v01);
            actOut[r1 * SA + pp]     = totf32(v10);
            actOut[r1 * SA + pp + 2] = totf32(v11);
        }
    }
}

// epilogue -> plain-layout store (consumed by scalar dot, not mma)
static __device__ __forceinline__ void epi_plain(
    float acc[2][8][4], float* actOut, const float* __restrict__ bias,
    int mband, int nhalf, int lid)
{
    int gr = lid >> 2, j = lid & 3;
#pragma unroll
    for (int mf = 0; mf < 2; mf++) {
        int r0 = mband * 32 + mf * 16 + gr, r1 = r0 + 8;
#pragma unroll
        for (int nf = 0; nf < 8; nf++) {
            int col = nhalf * 64 + nf * 8 + 2 * j;
            float b0 = __ldg(bias + col), b1 = __ldg(bias + col + 1);
            *(float2*)(actOut + r0 * SA + col) =
                make_float2(silu_f(acc[mf][nf][0] + b0), silu_f(acc[mf][nf][1] + b1));
            *(float2*)(actOut + r1 * SA + col) =
                make_float2(silu_f(acc[mf][nf][2] + b0), silu_f(acc[mf][nf][3] + b1));
        }
    }
}

// ---------------- setup kernels ----------------
__global__ void zero_kernel() {
    int i = blockIdx.x * 256 + threadIdx.x;
    if (i < N_NODES * 128) g_agg[i] = 0.f;
    int j = i - N_NODES * 128;
    if (j >= 0 && j < N_NODES * 3) g_trans[j] = 0.f;
    int k = j - N_NODES * 3;
    if (k >= 0 && k < N_NODES) g_cnt[k] = 0.f;
}

__global__ void prep_kernel(
    const float* __restrict__ mw0, const float* __restrict__ mw1,
    const float* __restrict__ cw0, const float* __restrict__ cw1,
    const float* __restrict__ nw0, const float* __restrict__ nw1,
    const float* __restrict__ nw2)
{
    int t = blockIdx.x * 256 + threadIdx.x;
    if (t >= 9 * 16384) return;
    int slot = t >> 14, r = t & 16383;
    int k = r >> 7, n = r & 127;
    const float* W; int kb = 0;
    switch (slot) {
        case 0: W = mw0; break;
        case 1: W = mw0; kb = 128; break;
        case 2: W = mw1; break;
        case 3: W = cw0; break;
        case 4: W = cw1; break;
        case 5: W = nw0; break;
        case 6: W = nw0; kb = 128; break;
        case 7: W = nw1; break;
        default: W = nw2; break;
    }
    float v = W[(kb + k) * 128 + n];
    int u = k & 7;
    int kp = (k & ~7) + ((u & 3) * 2 + (u >> 2));   // pair-interleave within 8
    g_wprep[slot * 16384 + n * 128 + kp] = totf32(v);   // transposed: [n][kperm]
}

// ---------------- main kernels ----------------
#define SMEM_BYTES ((128 * SA * 2 + 128 * SW + 768) * 4)

__global__ __launch_bounds__(256, 1) void edge_kernel(
    const float* __restrict__ h, const float* __restrict__ coord,
    const float* __restrict__ mw0, const float* __restrict__ mb0,
    const float* __restrict__ mb1, const float* __restrict__ cb0,
    const float* __restrict__ cb1, const float* __restrict__ cw2,
    const int* __restrict__ ei)
{
    extern __shared__ float sm[];
    float* actA = sm;
    float* actB = actA + 128 * SA;
    float* Wsm  = actB + 128 * SA;
    float* ex   = Wsm + 128 * SW;
    int* s_row = (int*)ex;
    int* s_col = s_row + 128;
    float* s_rad = (float*)(s_col + 128);
    float* s_dx = s_rad + 128;
    float* s_dy = s_dx + 128;
    float* s_dz = s_dy + 128;

    int tid = threadIdx.x, lid = tid & 31, wid = tid >> 5;
    int mband = wid >> 1, nhalf = wid & 1;

    if (tid < 128) {
        int e = blockIdx.x * 128 + tid;
        int r = ei[2 * e], c = ei[2 * e + 1];
        s_row[tid] = r; s_col[tid] = c;
        float dx = coord[r * 3 + 0] - coord[c * 3 + 0];
        float dy = coord[r * 3 + 1] - coord[c * 3 + 1];
        float dz = coord[r * 3 + 2] - coord[c * 3 + 2];
        s_dx[tid] = dx; s_dy[tid] = dy; s_dz[tid] = dz;
        s_rad[tid] = dx * dx + dy * dy + dz * dz;
    }
    __syncthreads();

    gatherA(actA, h, s_row, tid, nullptr);
    gatherA(actB, h, s_col, tid, nullptr);
    fillW(Wsm, g_wprep + 0 * 16384, tid);
    __syncthreads();

    float acc[2][8][4];
    ZERO_ACC(acc);
    gemm_tile(actA, Wsm, acc, mband, nhalf, lid);   // h[row] @ mw0[0:128)
    __syncthreads();
    fillW(Wsm, g_wprep + 1 * 16384, tid);
    __syncthreads();
    gemm_tile(actB, Wsm, acc, mband, nhalf, lid);   // += h[col] @ mw0[128:256)
    // x1 = silu(acc + mb0 + rad * mw0[256]) -> actA
    epi_perm<true, false>(acc, actA, mb0, mw0 + 256 * 128, s_rad, nullptr,
                          mband, nhalf, lid);
    __syncthreads();
    fillW(Wsm, g_wprep + 2 * 16384, tid);
    __syncthreads();

    ZERO_ACC(acc);
    gemm_tile(actA, Wsm, acc, mband, nhalf, lid);   // @ mw1
    // m = silu(+mb1) -> actB ; scatter to g_agg
    epi_perm<false, true>(acc, actB, mb1, nullptr, nullptr, s_row,
                          mband, nhalf, lid);
    __syncthreads();
    fillW(Wsm, g_wprep + 3 * 16384, tid);
    __syncthreads();

    ZERO_ACC(acc);
    gemm_tile(actB, Wsm, acc, mband, nhalf, lid);   // @ cw0
    epi_perm<false, false>(acc, actA, cb0, nullptr, nullptr, nullptr,
                           mband, nhalf, lid);
    __syncthreads();
    fillW(Wsm, g_wprep + 4 * 16384, tid);
    __syncthreads();

    ZERO_ACC(acc);
    gemm_tile(actA, Wsm, acc, mband, nhalf, lid);   // @ cw1
    epi_plain(acc, actB, cb1, mband, nhalf, lid);   // phi2 -> actB (plain)
    __syncthreads();

    // phi_x = phi2 . cw2 ; trans/count scatter
    if (tid < 128) {
        float s = 0.f;
        const float* row = actB + tid * SA;
#pragma unroll
        for (int c = 0; c < 128; c += 4) {
            float4 p = *(const float4*)(row + c);
            s += p.x * __ldg(cw2 + c) + p.y * __ldg(cw2 + c + 1)
               + p.z * __ldg(cw2 + c + 2) + p.w * __ldg(cw2 + c + 3);
        }
        int node = s_row[tid];
        atomicAdd(&g_trans[node * 3 + 0], s_dx[tid] * s);
        atomicAdd(&g_trans[node * 3 + 1], s_dy[tid] * s);
        atomicAdd(&g_trans[node * 3 + 2], s_dz[tid] * s);
        atomicAdd(&g_cnt[node], 1.f);
    }
}

__global__ __launch_bounds__(256, 1) void node_kernel(
    const float* __restrict__ h, const float* __restrict__ coord,
    const float* __restrict__ nb0, const float* __restrict__ nb1,
    const float* __restrict__ nb2, float* __restrict__ out)
{
    extern __shared__ float sm[];
    float* actA = sm;
    float* actB = actA + 128 * SA;
    float* Wsm  = actB + 128 * SA;
    float* ex   = Wsm + 128 * SW;
    int* s_idx = (int*)ex;
    float* s_inv = (float*)(s_idx + 128);

    int tid = threadIdx.x, lid = tid & 31, wid = tid >> 5;
    int mband = wid >> 1, nhalf = wid & 1;
    int n0 = blockIdx.x * 128;

    if (tid < 128) {
        int n = n0 + tid;
        int nc = (n < N_NODES) ? n : (N_NODES - 1);
        s_idx[tid] = nc;
        s_inv[tid] = 1.f / fmaxf(g_cnt[nc], 1.f);
    }
    __syncthreads();

    gatherA(actA, h, s_idx, tid, nullptr);
    gatherA(actB, g_agg, s_idx, tid, s_inv);   // agg mean
    fillW(Wsm, g_wprep + 5 * 16384, tid);
    __syncthreads();

    float acc[2][8][4];
    ZERO_ACC(acc);
    gemm_tile(actA, Wsm, acc, mband, nhalf, lid);   // h @ nw0[0:128)
    __syncthreads();
    fillW(Wsm, g_wprep + 6 * 16384, tid);
    __syncthreads();
    gemm_tile(actB, Wsm, acc, mband, nhalf, lid);   // += agg @ nw0[128:256)
    epi_perm<false, false>(acc, actA, nb0, nullptr, nullptr, nullptr,
                           mband, nhalf, lid);
    __syncthreads();
    fillW(Wsm, g_wprep + 7 * 16384, tid);
    __syncthreads();

    ZERO_ACC(acc);
    gemm_tile(actA, Wsm, acc, mband, nhalf, lid);   // @ nw1
    epi_perm<false, false>(acc, actB, nb1, nullptr, nullptr, nullptr,
                           mband, nhalf, lid);
    __syncthreads();
    fillW(Wsm, g_wprep + 8 * 16384, tid);
    __syncthreads();

    ZERO_ACC(acc);
    gemm_tile(actB, Wsm, acc, mband, nhalf, lid);   // @ nw2

    // h_new = h + (acc + nb2), written straight to gmem
    {
        int gr = lid >> 2, j = lid & 3;
#pragma unroll
        for (int mf = 0; mf < 2; mf++) {
            int r0 = mband * 32 + mf * 16 + gr;
#pragma unroll
            for (int rr = 0; rr < 2; rr++) {
                int r = r0 + rr * 8;
                int n = n0 + r;
                if (n < N_NODES) {
#pragma unroll
                    for (int nf = 0; nf < 8; nf++) {
                        int col = nhalf * 64 + nf * 8 + 2 * j;
                        float2 hv = *(const float2*)(h + (size_t)n * 128 + col);
                        float a0 = acc[mf][nf][rr * 2 + 0];
                        float a1 = acc[mf][nf][rr * 2 + 1];
                        float2 q = make_float2(
                            hv.x + a0 + __ldg(nb2 + col),
                            hv.y + a1 + __ldg(nb2 + col + 1));
                        *(float2*)(out + (size_t)n * 128 + col) = q;
                    }
                }
            }
        }
    }
    // coord_new = coord + trans_mean
    if (tid < 128) {
        int n = n0 + tid;
        if (n < N_NODES) {
            float inv = s_inv[tid];
            float* co = out + (size_t)N_NODES * 128 + n * 3;
            co[0] = coord[n * 3 + 0] + g_trans[n * 3 + 0] * inv;
            co[1] = coord[n * 3 + 1] + g_trans[n * 3 + 1] * inv;
            co[2] = coord[n * 3 + 2] + g_trans[n * 3 + 2] * inv;
        }
    }
}

// ---------------- launcher ----------------
extern "C" void kernel_launch(void* const* d_in, const int* in_sizes, int n_in,
                              void* d_out, int out_size)
{
    const float* h   = (const float*)d_in[0];
    const float* coord = (const float*)d_in[1];
    const float* mw0 = (const float*)d_in[2];
    const float* mb0 = (const float*)d_in[3];
    const float* mw1 = (const float*)d_in[4];
    const float* mb1 = (const float*)d_in[5];
    const float* nw0 = (const float*)d_in[6];
    const float* nb0 = (const float*)d_in[7];
    const float* nw1 = (const float*)d_in[8];
    const float* nb1 = (const float*)d_in[9];
    const float* nw2 = (const float*)d_in[10];
    const float* nb2 = (const float*)d_in[11];
    const float* cw0 = (const float*)d_in[12];
    const float* cb0 = (const float*)d_in[13];
    const float* cw1 = (const float*)d_in[14];
    const float* cb1 = (const float*)d_in[15];
    const float* cw2 = (const float*)d_in[16];
    const int* ei = (const int*)d_in[17];
    float* out = (float*)d_out;

    cudaFuncSetAttribute(edge_kernel,
        cudaFuncAttributeMaxDynamicSharedMemorySize, SMEM_BYTES);
    cudaFuncSetAttribute(node_kernel,
        cudaFuncAttributeMaxDynamicSharedMemorySize, SMEM_BYTES);

    int totalz = N_NODES * 128 + N_NODES * 3 + N_NODES;
    zero_kernel<<<(totalz + 255) / 256, 256>>>();
    prep_kernel<<<(9 * 16384 + 255) / 256, 256>>>(mw0, mw1, cw0, cw1, nw0, nw1, nw2);
    edge_kernel<<<N_EDGES / 128, 256, SMEM_BYTES>>>(
        h, coord, mw0, mb0, mb1, cb0, cb1, cw2, ei);
    node_kernel<<<(N_NODES + 127) / 128, 256, SMEM_BYTES>>>(
        h, coord, nb0, nb1, nb2, out);
}